// round 6
// baseline (speedup 1.0000x reference)
#include <cuda_runtime.h>
#include <cstdint>

// Masked row-wise cumsum: out[r,:] = cumsum(x[r,:] * mask[r,:])
// x: f32 [4096, 32768]; mask: 4-byte 0/1 words on the wire (byte fallback
// kept); out: f32 [4096, 32768].
//
// One CTA per row, 256 threads x 4 elems = 1024-elem chunks, 32 chunks/row.
// 8 CTAs/SM (launch_bounds(256,8)) -> eight independent load/scan/store
// phase streams per SM (R5 confirmed: stream count is the lever that raises
// DRAM%). Streaming cache hints since there is zero reuse. One barrier per
// chunk via ping-pong warp totals + redundant per-warp scan of 8 totals.

#ifndef CUMSUM_N
#define CUMSUM_N 32768
#endif

#define TPB   256
#define VEC   4
#define CHUNK (TPB * VEC)   // 1024
#define NWARP (TPB / 32)    // 8

__global__ __launch_bounds__(TPB, 8)
void masked_cumsum_row_kernel(const float* __restrict__ x,
                              const void* __restrict__ mask,
                              float* __restrict__ out,
                              int n_cols)
{
    const int row   = blockIdx.x;
    const size_t base = (size_t)row * (size_t)n_cols;

    const int tid  = threadIdx.x;
    const int lane = tid & 31;
    const int wid  = tid >> 5;

    // --- per-warp mask dtype detection (deterministic, no barrier) ---
    // First 32 words: a 4-byte 0/1 encoding only yields 0, 1 (int32) or
    // 0x3F800000 (f32 1.0); random 0/1 BYTES produce other words w.p. 7/8.
    const unsigned probe = ((const unsigned*)mask)[lane];
    const bool clean = (probe == 0u) | (probe == 1u) | (probe == 0x3F800000u);
    const bool word_mode = __all_sync(0xffffffffu, clean);

    __shared__ float s_warp[2][NWARP];

    float carry = 0.0f;
    int p = 0;

    #pragma unroll 1
    for (int c = 0; c < n_cols; c += CHUNK) {
        const size_t off = base + (size_t)c + (size_t)tid * VEC;

        const float4 xv = __ldcs(reinterpret_cast<const float4*>(x + off));

        float v0, v1, v2, v3;
        if (word_mode) {
            const uint4 mv = __ldcs(reinterpret_cast<const uint4*>((const unsigned*)mask + off));
            v0 = mv.x ? xv.x : 0.f;
            v1 = mv.y ? xv.y : 0.f;
            v2 = mv.z ? xv.z : 0.f;
            v3 = mv.w ? xv.w : 0.f;
        } else {
            const unsigned mv = __ldcs(reinterpret_cast<const unsigned*>((const uint8_t*)mask + off));
            v0 = (mv & 0x000000FFu) ? xv.x : 0.f;
            v1 = (mv & 0x0000FF00u) ? xv.y : 0.f;
            v2 = (mv & 0x00FF0000u) ? xv.z : 0.f;
            v3 = (mv & 0xFF000000u) ? xv.w : 0.f;
        }

        // thread-local inclusive scan of 4
        const float s0 = v0;
        const float s1 = s0 + v1;
        const float s2 = s1 + v2;
        const float s3 = s2 + v3;

        // warp inclusive scan of per-thread totals
        float t = s3;
        #pragma unroll
        for (int d = 1; d < 32; d <<= 1) {
            float nv = __shfl_up_sync(0xffffffffu, t, d);
            if (lane >= d) t += nv;
        }
        const float thread_excl = t - s3;

        if (lane == 31) s_warp[p][wid] = t;
        __syncthreads();                      // the ONLY barrier per chunk

        // every warp redundantly scans the 8 warp totals (3 shfl steps)
        float wincl = (lane < NWARP) ? s_warp[p][lane] : 0.f;
        #pragma unroll
        for (int d = 1; d < NWARP; d <<= 1) {
            float nv = __shfl_up_sync(0xffffffffu, wincl, d);
            if (lane >= d) wincl += nv;
        }
        const float warp_excl = (wid == 0)
            ? 0.f
            : __shfl_sync(0xffffffffu, wincl, wid - 1);
        const float block_tot = __shfl_sync(0xffffffffu, wincl, NWARP - 1);

        const float offv = carry + warp_excl + thread_excl;

        float4 o;
        o.x = s0 + offv;
        o.y = s1 + offv;
        o.z = s2 + offv;
        o.w = s3 + offv;
        __stcs(reinterpret_cast<float4*>(out + off), o);

        carry += block_tot;
        p ^= 1;    // ping-pong -> no trailing barrier needed
    }
}

extern "C" void kernel_launch(void* const* d_in, const int* in_sizes, int n_in,
                              void* d_out, int out_size)
{
    const float* x    = (const float*)d_in[0];
    const void*  mask = d_in[1];
    float*       out  = (float*)d_out;

    const int n_cols = CUMSUM_N;
    const int n_rows = in_sizes[0] / n_cols;   // 4096

    masked_cumsum_row_kernel<<<n_rows, TPB>>>(x, mask, out, n_cols);
}